// round 8
// baseline (speedup 1.0000x reference)
#include <cuda_runtime.h>
#include <cuda_bf16.h>
#include <cstdint>

#define NH 32
#define NKV 8
#define SQ 2048
#define NBATCH 2
#define WIN 1024
#define SM_SCALE 0.08838834764831845f
#define BM 128
#define BN 64
#define HD 128
#define THREADS 512

// ---- bf16 hi/lo scratch (filled by prep kernel once per launch) ----
#define KVELEMS (NBATCH * NKV * SQ * HD)
__device__ __align__(16) uint16_t KHIg[KVELEMS];
__device__ __align__(16) uint16_t KLOg[KVELEMS];
__device__ __align__(16) uint16_t VHIg[KVELEMS];
__device__ __align__(16) uint16_t VLOg[KVELEMS];

// smem byte offsets
#define QHI_B 0u
#define QLO_B 34816u
#define KB0   69632u          // K buffer 0: KHI +0, KLO +17408
#define KB1   104448u
#define VB    139264u         // VHI +0, VLO +17408
#define PHI_B 174080u         // P hi: 128 rows x 72 bf16 (stride 144B)
#define PLO_B 192512u
#define LRED_B 210944u        // 2 x 128 floats
#define SMEM_BYTES 211968
#define KARR 17408u
#define PARR 18432u

__device__ __forceinline__ uint32_t smaddr(const void* p) {
    uint32_t a;
    asm("{ .reg .u64 t; cvta.to.shared.u64 t, %1; cvt.u32.u64 %0, t; }" : "=r"(a) : "l"(p));
    return a;
}
__device__ __forceinline__ uint32_t packbf(float f0, float f1) {
    uint32_t d;
    asm("cvt.rn.bf16x2.f32 %0, %1, %2;" : "=r"(d) : "f"(f1), "f"(f0));
    return d;
}
__device__ __forceinline__ void split2(float f0, float f1, uint32_t& hi2, uint32_t& lo2) {
    hi2 = packbf(f0, f1);
    float h0 = __uint_as_float(hi2 << 16);
    float h1 = __uint_as_float(hi2 & 0xffff0000u);
    lo2 = packbf(f0 - h0, f1 - h1);
}
__device__ __forceinline__ void ldsm4(uint32_t a, uint32_t* r) {
    asm volatile("ldmatrix.sync.aligned.m8n8.x4.shared.b16 {%0,%1,%2,%3}, [%4];"
        : "=r"(r[0]), "=r"(r[1]), "=r"(r[2]), "=r"(r[3]) : "r"(a));
}
__device__ __forceinline__ void ldsm4t(uint32_t a, uint32_t* r) {
    asm volatile("ldmatrix.sync.aligned.m8n8.x4.trans.shared.b16 {%0,%1,%2,%3}, [%4];"
        : "=r"(r[0]), "=r"(r[1]), "=r"(r[2]), "=r"(r[3]) : "r"(a));
}
__device__ __forceinline__ void mma16816(float* c, const uint32_t* a, const uint32_t* b) {
    asm volatile("mma.sync.aligned.m16n8k16.row.col.f32.bf16.bf16.f32 "
        "{%0,%1,%2,%3}, {%4,%5,%6,%7}, {%8,%9}, {%0,%1,%2,%3};"
        : "+f"(c[0]), "+f"(c[1]), "+f"(c[2]), "+f"(c[3])
        : "r"(a[0]), "r"(a[1]), "r"(a[2]), "r"(a[3]), "r"(b[0]), "r"(b[1]));
}
__device__ __forceinline__ void cpa16(uint32_t saddr, const void* gaddr) {
    asm volatile("cp.async.cg.shared.global [%0], [%1], 16;" :: "r"(saddr), "l"(gaddr));
}
#define CP_COMMIT() asm volatile("cp.async.commit_group;" ::: "memory")
#define CP_WAIT1()  asm volatile("cp.async.wait_group 1;" ::: "memory")

// ---- prep: fp32 K/V -> bf16 hi/lo scratch, [b][hk][s][d] ----
__global__ __launch_bounds__(256)
void prep_kv(const float* __restrict__ Kg, const float* __restrict__ Vg)
{
    int i = blockIdx.x * blockDim.x + threadIdx.x;
    int d4 = (i & 31) << 2;
    int hk = (i >> 5) & 7;
    int s  = (i >> 8) & 2047;
    int b  = i >> 19;
    size_t in  = ((size_t)(b * SQ + s)) * (NKV * HD) + hk * HD + d4;
    size_t out = (((size_t)(b * NKV + hk)) * SQ + s) * HD + d4;

    float4 v = *(const float4*)(Kg + in);
    uint32_t h01, l01, h23, l23;
    split2(v.x, v.y, h01, l01);
    split2(v.z, v.w, h23, l23);
    *(uint2*)&KHIg[out] = make_uint2(h01, h23);
    *(uint2*)&KLOg[out] = make_uint2(l01, l23);

    float4 w = *(const float4*)(Vg + in);
    split2(w.x, w.y, h01, l01);
    split2(w.z, w.w, h23, l23);
    *(uint2*)&VHIg[out] = make_uint2(h01, h23);
    *(uint2*)&VLOg[out] = make_uint2(l01, l23);
}

__device__ __forceinline__ void issue_k(uint32_t sb, uint32_t kbuf, int tid, size_t kvrow0)
{
    #pragma unroll
    for (int i = 0; i < 4; i++) {
        const int arr = i >> 1;
        int idx = (i & 1) * 512 + tid;
        int row = idx >> 4, ch8 = (idx & 15) * 8;
        const uint16_t* gb = arr ? KLOg : KHIg;
        cpa16(sb + kbuf + (uint32_t)arr * KARR + (uint32_t)(row * 136 + ch8) * 2u,
              gb + (kvrow0 + row) * HD + ch8);
    }
}
__device__ __forceinline__ void issue_v(uint32_t sb, int tid, size_t kvrow0)
{
    #pragma unroll
    for (int i = 0; i < 4; i++) {
        const int arr = i >> 1;
        int idx = (i & 1) * 512 + tid;
        int row = idx >> 4, ch8 = (idx & 15) * 8;
        const uint16_t* gb = arr ? VLOg : VHIg;
        cpa16(sb + VB + (uint32_t)arr * KARR + (uint32_t)(row * 136 + ch8) * 2u,
              gb + (kvrow0 + row) * HD + ch8);
    }
}

__global__ __launch_bounds__(THREADS, 1)
void attn_hmma(const float* __restrict__ Qg, float* __restrict__ Og)
{
    extern __shared__ __align__(16) char smch[];
    const uint32_t sb = smaddr(smch);

    const int tid = threadIdx.x;
    const int wid = tid >> 5, lane = tid & 31;
    const int g = lane >> 2, tg = lane & 3;
    const int wq = wid >> 1, wk = wid & 1;
    const int r0 = wq * 16;

    const int qt = blockIdx.x, h = blockIdx.y, b = blockIdx.z;
    const int hk = h >> 2;
    const int q0 = qt * BM;

    const float* Qb = Qg + ((size_t)b * SQ) * (NH * HD) + (size_t)h * HD;
    const size_t kvbase = ((size_t)(b * NKV + hk)) * SQ;

    // ---- Q tile -> smem hi/lo ----
    #pragma unroll
    for (int i = 0; i < 8; i++) {
        int c = tid + i * THREADS;
        int r = c >> 5, d4 = (c & 31) << 2;
        float4 v = *(const float4*)(Qb + (size_t)(q0 + r) * (NH * HD) + d4);
        uint32_t h01, l01, h23, l23;
        split2(v.x, v.y, h01, l01);
        split2(v.z, v.w, h23, l23);
        *(uint2*)(smch + QHI_B + (r * 136 + d4) * 2) = make_uint2(h01, h23);
        *(uint2*)(smch + QLO_B + (r * 136 + d4) * 2) = make_uint2(l01, l23);
    }

    // per-thread ldmatrix relative addrs
    const uint32_t qa_rel = (uint32_t)((r0 + (lane & 15)) * 272 + ((lane >> 4) & 1) * 16);
    const uint32_t ka_rel = (uint32_t)(((lane & 7) + ((lane >> 4) & 1) * 8 + wk * 32) * 272
                                       + ((lane >> 3) & 1) * 16);
    const uint32_t va_rel = (uint32_t)((lane & 15) * 272 + ((lane >> 4) & 1) * 16 + wk * 128);
    const uint32_t pa_rel = (uint32_t)((r0 + (lane & 15)) * 144 + ((lane >> 4) & 1) * 16);

    float oacc[8][4];
    #pragma unroll
    for (int nb = 0; nb < 8; nb++)
        #pragma unroll
        for (int j = 0; j < 4; j++) oacc[nb][j] = 0.f;
    float lsum0 = 0.f, lsum1 = 0.f;

    int lo_k = q0 - (WIN - 1); if (lo_k < 0) lo_k = 0;
    const int t0 = lo_k >> 6;
    const int t1 = (q0 + BM - 1) >> 6;

    // prologue: K(t0), V(t0)
    issue_k(sb, KB0, tid, kvbase + ((size_t)t0 << 6));
    CP_COMMIT();
    issue_v(sb, tid, kvbase + ((size_t)t0 << 6));
    CP_COMMIT();

    for (int t = t0; t <= t1; ++t) {
        const int k0 = t << 6;
        const uint32_t kcur = ((t - t0) & 1) ? KB1 : KB0;
        const uint32_t knxt = ((t - t0) & 1) ? KB0 : KB1;

        if (t < t1)
            issue_k(sb, knxt, tid, kvbase + ((size_t)(t + 1) << 6));
        CP_COMMIT();
        CP_WAIT1();
        __syncthreads();

        // ---- QK^T: 16 rows x 32 keys (this warp's half), bf16x3 ----
        const uint32_t qah = sb + QHI_B + qa_rel;
        const uint32_t kah = sb + kcur + ka_rel;
        float sacc[4][4];
        #pragma unroll
        for (int nb = 0; nb < 4; nb++)
            #pragma unroll
            for (int j = 0; j < 4; j++) sacc[nb][j] = 0.f;

        #pragma unroll
        for (int kb = 0; kb < 8; kb++) {
            uint32_t ah[4], al[4];
            ldsm4(qah + kb * 32, ah);
            ldsm4(qah + (QLO_B - QHI_B) + kb * 32, al);
            #pragma unroll
            for (int np = 0; np < 2; np++) {
                uint32_t bh[4], bl[4];
                ldsm4(kah + np * 4352 + kb * 32, bh);
                ldsm4(kah + KARR + np * 4352 + kb * 32, bl);
                mma16816(sacc[2 * np],     ah, bh);
                mma16816(sacc[2 * np + 1], ah, bh + 2);
                mma16816(sacc[2 * np],     ah, bl);
                mma16816(sacc[2 * np + 1], ah, bl + 2);
                mma16816(sacc[2 * np],     al, bh);
                mma16816(sacc[2 * np + 1], al, bh + 2);
            }
        }

        // ---- softmax + P hi/lo -> smem ----
        const int k0w = k0 + wk * 32;
        const bool allfull = (k0w + 31 <= q0 + r0) && ((q0 + r0 + 15) - k0w < WIN);
        #pragma unroll
        for (int nb = 0; nb < 4; nb++) {
            float p[4];
            #pragma unroll
            for (int j = 0; j < 4; j++) {
                float pv = __expf(sacc[nb][j] * SM_SCALE);
                if (!allfull) {
                    int key = k0w + nb * 8 + 2 * tg + (j & 1);
                    int row = q0 + r0 + g + ((j >> 1) << 3);
                    bool ok = (key <= row) && (row - key < WIN);
                    pv = ok ? pv : 0.f;
                }
                p[j] = pv;
            }
            lsum0 += p[0] + p[1];
            lsum1 += p[2] + p[3];
            uint32_t h0, l0, h1, l1;
            split2(p[0], p[1], h0, l0);
            split2(p[2], p[3], h1, l1);
            uint32_t koff = (uint32_t)(wk * 32 + nb * 8 + 2 * tg);
            uint32_t a0 = sb + PHI_B + ((uint32_t)(r0 + g) * 72 + koff) * 2;
            uint32_t a1 = sb + PHI_B + ((uint32_t)(r0 + g + 8) * 72 + koff) * 2;
            *(uint32_t*)(smch + (a0 - sb)) = h0;
            *(uint32_t*)(smch + (a1 - sb)) = h1;
            *(uint32_t*)(smch + (a0 - sb) + PARR) = l0;
            *(uint32_t*)(smch + (a1 - sb) + PARR) = l1;
        }
        __syncthreads();   // partner warp's P half visible

        // ---- PV: 16 rows x 64 d (this warp's half), bf16x3 ----
        const uint32_t pah = sb + PHI_B + pa_rel;
        const uint32_t vah = sb + VB + va_rel;
        #pragma unroll
        for (int kb = 0; kb < 4; kb++) {
            uint32_t ap[4], alp[4];
            ldsm4(pah + kb * 32, ap);
            ldsm4(pah + PARR + kb * 32, alp);
            #pragma unroll
            for (int np = 0; np < 4; np++) {
                uint32_t vh[4], vl[4];
                ldsm4t(vah + kb * 4352 + np * 32, vh);
                ldsm4t(vah + KARR + kb * 4352 + np * 32, vl);
                mma16816(oacc[2 * np],     ap, vh);
                mma16816(oacc[2 * np + 1], ap, vh + 2);
                mma16816(oacc[2 * np],     ap, vl);
                mma16816(oacc[2 * np + 1], ap, vl + 2);
                mma16816(oacc[2 * np],     alp, vh);
                mma16816(oacc[2 * np + 1], alp, vh + 2);
            }
        }
        __syncthreads();   // V + P buffers free

        if (t < t1) {
            issue_v(sb, tid, kvbase + ((size_t)(t + 1) << 6));
            CP_COMMIT();
        }
    }

    // ---- lsum: intra-warp (tg) then cross-warp via smem ----
    lsum0 += __shfl_xor_sync(0xffffffffu, lsum0, 1);
    lsum0 += __shfl_xor_sync(0xffffffffu, lsum0, 2);
    lsum1 += __shfl_xor_sync(0xffffffffu, lsum1, 1);
    lsum1 += __shfl_xor_sync(0xffffffffu, lsum1, 2);
    float* Lr = (float*)(smch + LRED_B);
    if (tg == 0) {
        Lr[wk * 128 + r0 + g] = lsum0;
        Lr[wk * 128 + r0 + g + 8] = lsum1;
    }
    __syncthreads();
    const float inv0 = 1.f / (Lr[r0 + g] + Lr[128 + r0 + g]);
    const float inv1 = 1.f / (Lr[r0 + g + 8] + Lr[128 + r0 + g + 8]);

    // ---- store O ----
    const int row0 = q0 + r0 + g;
    float* o0 = Og + ((size_t)b * SQ + row0) * (NH * HD) + (size_t)h * HD + wk * 64;
    float* o1 = o0 + 8 * (size_t)(NH * HD);
    #pragma unroll
    for (int nb = 0; nb < 8; nb++) {
        int col = nb * 8 + 2 * tg;
        *(float2*)(o0 + col) = make_float2(oacc[nb][0] * inv0, oacc[nb][1] * inv0);
        *(float2*)(o1 + col) = make_float2(oacc[nb][2] * inv1, oacc[nb][3] * inv1);
    }
}

extern "C" void kernel_launch(void* const* d_in, const int* in_sizes, int n_in,
                              void* d_out, int out_size)
{
    const float* Q = (const float*)d_in[0];
    const float* K = (const float*)d_in[1];
    const float* V = (const float*)d_in[2];
    float* O = (float*)d_out;

    prep_kv<<<KVELEMS / 4 / 256, 256>>>(K, V);

    cudaFuncSetAttribute(attn_hmma, cudaFuncAttributeMaxDynamicSharedMemorySize, SMEM_BYTES);
    dim3 grid(SQ / BM, NH, NBATCH);
    attn_hmma<<<grid, THREADS, SMEM_BYTES>>>(Q, O);
}

// round 10
// speedup vs baseline: 1.1230x; 1.1230x over previous
#include <cuda_runtime.h>
#include <cuda_bf16.h>
#include <cstdint>

#define NH 32
#define NKV 8
#define SQ 2048
#define NBATCH 2
#define WIN 1024
#define SM_SCALE 0.08838834764831845f
#define BM 128
#define BN 64
#define HD 128
#define THREADS 256

// ---- bf16 hi/lo scratch (filled by prep kernel once per launch) ----
#define KVELEMS (NBATCH * NKV * SQ * HD)
__device__ __align__(16) uint16_t KHIg[KVELEMS];
__device__ __align__(16) uint16_t KLOg[KVELEMS];
__device__ __align__(16) uint16_t VHIg[KVELEMS];
__device__ __align__(16) uint16_t VLOg[KVELEMS];

// smem layout (bytes): Q hi/lo static; K/V hi/lo double-buffered
#define QSTR 136
#define KSTR 136
#define VSTR 136
#define QHI_B 0
#define QLO_B (BM * QSTR * 2)                  // 34816
#define QREG  (2 * BM * QSTR * 2)              // 69632
#define ARRB  (BN * KSTR * 2)                  // 17408 per array
#define BUFSZ (4 * ARRB)                       // 69632 per buffer
#define KHI_O 0
#define KLO_O ARRB
#define VHI_O (2 * ARRB)
#define VLO_O (3 * ARRB)
#define LO_OFF ARRB
#define SMEM_BYTES (QREG + 2 * BUFSZ + 16)     // ~204 KB

__device__ __forceinline__ uint32_t smaddr(const void* p) {
    uint32_t a;
    asm("{ .reg .u64 t; cvta.to.shared.u64 t, %1; cvt.u32.u64 %0, t; }" : "=r"(a) : "l"(p));
    return a;
}
__device__ __forceinline__ uint32_t packbf(float f0, float f1) {
    uint32_t d;
    asm("cvt.rn.bf16x2.f32 %0, %1, %2;" : "=r"(d) : "f"(f1), "f"(f0));
    return d;
}
__device__ __forceinline__ void split2(float f0, float f1, uint32_t& hi2, uint32_t& lo2) {
    hi2 = packbf(f0, f1);
    float h0 = __uint_as_float(hi2 << 16);
    float h1 = __uint_as_float(hi2 & 0xffff0000u);
    lo2 = packbf(f0 - h0, f1 - h1);
}
__device__ __forceinline__ void ldsm4(uint32_t a, uint32_t* r) {
    asm volatile("ldmatrix.sync.aligned.m8n8.x4.shared.b16 {%0,%1,%2,%3}, [%4];"
        : "=r"(r[0]), "=r"(r[1]), "=r"(r[2]), "=r"(r[3]) : "r"(a));
}
__device__ __forceinline__ void ldsm4t(uint32_t a, uint32_t* r) {
    asm volatile("ldmatrix.sync.aligned.m8n8.x4.trans.shared.b16 {%0,%1,%2,%3}, [%4];"
        : "=r"(r[0]), "=r"(r[1]), "=r"(r[2]), "=r"(r[3]) : "r"(a));
}
__device__ __forceinline__ void mma16816(float* c, const uint32_t* a, const uint32_t* b) {
    asm volatile("mma.sync.aligned.m16n8k16.row.col.f32.bf16.bf16.f32 "
        "{%0,%1,%2,%3}, {%4,%5,%6,%7}, {%8,%9}, {%0,%1,%2,%3};"
        : "+f"(c[0]), "+f"(c[1]), "+f"(c[2]), "+f"(c[3])
        : "r"(a[0]), "r"(a[1]), "r"(a[2]), "r"(a[3]), "r"(b[0]), "r"(b[1]));
}
__device__ __forceinline__ void cpa16(uint32_t saddr, const void* gaddr) {
    asm volatile("cp.async.cg.shared.global [%0], [%1], 16;" :: "r"(saddr), "l"(gaddr));
}

// ---- prep: fp32 K/V -> bf16 hi/lo scratch, [b][hk][s][d] layout ----
__global__ __launch_bounds__(256)
void prep_kv(const float* __restrict__ Kg, const float* __restrict__ Vg)
{
    int i = blockIdx.x * blockDim.x + threadIdx.x;
    int d4 = (i & 31) << 2;
    int hk = (i >> 5) & 7;
    int s  = (i >> 8) & 2047;
    int b  = i >> 19;
    size_t in  = ((size_t)(b * SQ + s)) * (NKV * HD) + hk * HD + d4;
    size_t out = (((size_t)(b * NKV + hk)) * SQ + s) * HD + d4;

    float4 v = *(const float4*)(Kg + in);
    uint32_t h01, l01, h23, l23;
    split2(v.x, v.y, h01, l01);
    split2(v.z, v.w, h23, l23);
    *(uint2*)&KHIg[out] = make_uint2(h01, h23);
    *(uint2*)&KLOg[out] = make_uint2(l01, l23);

    float4 w = *(const float4*)(Vg + in);
    split2(w.x, w.y, h01, l01);
    split2(w.z, w.w, h23, l23);
    *(uint2*)&VHIg[out] = make_uint2(h01, h23);
    *(uint2*)&VLOg[out] = make_uint2(l01, l23);
}

// issue 16B cp.async chunks for one 64-row tile (all 4 arrays) into buf
__device__ __forceinline__ void issue_tile(uint32_t sb, uint32_t buf, int tid,
                                           size_t kvrow0)
{
    const int ch8 = (tid & 15) * 8;
    #pragma unroll
    for (int i = 0; i < 16; i++) {
        const int arr = i >> 2;
        const int r = ((i * 16) + (tid >> 4)) & 63;
        const uint16_t* gb = (arr == 0) ? KHIg : (arr == 1) ? KLOg
                           : (arr == 2) ? VHIg : VLOg;
        const void* g = gb + (kvrow0 + r) * HD + ch8;
        uint32_t s = sb + buf + (uint32_t)arr * ARRB + (uint32_t)(r * KSTR + ch8) * 2u;
        cpa16(s, g);
    }
}

__global__ __launch_bounds__(THREADS, 1)
void attn_hmma(const float* __restrict__ Qg, float* __restrict__ Og)
{
    extern __shared__ __align__(16) char smch[];
    const uint32_t sb = smaddr(smch);

    const int tid = threadIdx.x;
    const int wid = tid >> 5, lane = tid & 31;
    const int g = lane >> 2, tg = lane & 3;
    const int r0 = wid * 16;

    const int qt = blockIdx.x, h = blockIdx.y, b = blockIdx.z;
    const int hk = h >> 2;
    const int q0 = qt * BM;

    const float* Qb = Qg + ((size_t)b * SQ) * (NH * HD) + (size_t)h * HD;
    const size_t kvbase = ((size_t)(b * NKV + hk)) * SQ;

    // ---- Q tile -> smem hi/lo ----
    #pragma unroll
    for (int i = 0; i < 16; i++) {
        int c = tid + i * THREADS;
        int r = c >> 5, d4 = (c & 31) << 2;
        float4 v = *(const float4*)(Qb + (size_t)(q0 + r) * (NH * HD) + d4);
        uint32_t h01, l01, h23, l23;
        split2(v.x, v.y, h01, l01);
        split2(v.z, v.w, h23, l23);
        *(uint2*)(smch + QHI_B + (r * QSTR + d4) * 2) = make_uint2(h01, h23);
        *(uint2*)(smch + QLO_B + (r * QSTR + d4) * 2) = make_uint2(l01, l23);
    }

    // per-thread ldmatrix addrs
    const uint32_t qa = sb + QHI_B + ((r0 + (lane & 15)) * QSTR + ((lane >> 4) << 3)) * 2;
    // K x4 pairing: lanes 0-15 -> keys (pair*16 + 0..7)? mapping: matrices
    // m0,m1 = keys p*16..+7 (col halves), m2,m3 = keys p*16+8..+15
    const uint32_t ka_rel = (uint32_t)((((lane & 7) + ((lane >> 4) & 1) * 8) * KSTR
                                        + (((lane >> 3) & 1) << 3)) * 2);
    // V x4t pairing: per pair, 16 cols; lanes 0-15 rows, (lane>>4) selects col half
    const uint32_t va_rel = (uint32_t)((lane & 15) * (VSTR * 2) + (((lane >> 4) & 1) << 4));

    float oacc[16][4];
    #pragma unroll
    for (int nb = 0; nb < 16; nb++)
        #pragma unroll
        for (int j = 0; j < 4; j++) oacc[nb][j] = 0.f;
    float lsum0 = 0.f, lsum1 = 0.f;

    int lo_k = q0 - (WIN - 1); if (lo_k < 0) lo_k = 0;
    const int t0 = lo_k >> 6;
    const int t1 = (q0 + BM - 1) >> 6;

    issue_tile(sb, QREG, tid, kvbase + ((size_t)t0 << 6));
    asm volatile("cp.async.commit_group;" ::: "memory");

    for (int t = t0; t <= t1; ++t) {
        const int k0 = t << 6;
        const uint32_t bufc = QREG + ((t - t0) & 1) * BUFSZ;
        const uint32_t bufn = QREG + (((t - t0) + 1) & 1) * BUFSZ;

        if (t < t1)
            issue_tile(sb, bufn, tid, kvbase + ((size_t)(t + 1) << 6));
        asm volatile("cp.async.commit_group;" ::: "memory");
        asm volatile("cp.async.wait_group 1;" ::: "memory");
        __syncthreads();

        // ---- QK^T: bf16x3 HMMA, K loaded as x4 pairs ----
        const uint32_t ka = sb + bufc + KHI_O + ka_rel;
        float sacc[8][4];
        #pragma unroll
        for (int nb = 0; nb < 8; nb++)
            #pragma unroll
            for (int j = 0; j < 4; j++) sacc[nb][j] = 0.f;

        #pragma unroll
        for (int kb = 0; kb < 8; kb++) {
            uint32_t ah[4], al[4];
            ldsm4(qa + kb * 32, ah);
            ldsm4(qa + (QLO_B - QHI_B) + kb * 32, al);
            #pragma unroll
            for (int np = 0; np < 4; np++) {
                uint32_t bh[4], bl[4];
                ldsm4(ka + np * 4352 + kb * 32, bh);
                ldsm4(ka + LO_OFF + np * 4352 + kb * 32, bl);
                mma16816(sacc[2 * np],     ah, bh);
                mma16816(sacc[2 * np + 1], ah, bh + 2);
                mma16816(sacc[2 * np],     ah, bl);
                mma16816(sacc[2 * np + 1], ah, bl + 2);
                mma16816(sacc[2 * np],     al, bh);
                mma16816(sacc[2 * np + 1], al, bh + 2);
            }
        }

        // ---- softmax (no max-shift) + P hi/lo A-fragments ----
        uint32_t phi[4][4], plo[4][4];
        const bool allfull = (k0 + BN - 1 <= q0 + r0) && ((q0 + r0 + 15) - k0 < WIN);
        #pragma unroll
        for (int nb = 0; nb < 8; nb++) {
            float p[4];
            #pragma unroll
            for (int j = 0; j < 4; j++) {
                float pv = __expf(sacc[nb][j] * SM_SCALE);
                if (!allfull) {
                    int key = k0 + nb * 8 + 2 * tg + (j & 1);
                    int row = q0 + r0 + g + ((j >> 1) << 3);
                    bool ok = (key <= row) && (row - key < WIN);
                    pv = ok ? pv : 0.f;
                }
                p[j] = pv;
            }
            lsum0 += p[0] + p[1];
            lsum1 += p[2] + p[3];
            int kb2 = nb >> 1, hi = nb & 1;
            split2(p[0], p[1], phi[kb2][hi * 2 + 0], plo[kb2][hi * 2 + 0]);
            split2(p[2], p[3], phi[kb2][hi * 2 + 1], plo[kb2][hi * 2 + 1]);
        }

        // ---- PV: P (regs) x V (x4 trans pairs) ----
        const uint32_t va = sb + bufc + VHI_O + va_rel;
        #pragma unroll
        for (int kb = 0; kb < 4; kb++) {
            #pragma unroll
            for (int np = 0; np < 8; np++) {
                uint32_t vh[4], vl[4];
                ldsm4t(va + kb * 4352 + np * 32, vh);
                ldsm4t(va + LO_OFF + kb * 4352 + np * 32, vl);
                mma16816(oacc[2 * np],     phi[kb], vh);
                mma16816(oacc[2 * np + 1], phi[kb], vh + 2);
                mma16816(oacc[2 * np],     phi[kb], vl);
                mma16816(oacc[2 * np + 1], phi[kb], vl + 2);
                mma16816(oacc[2 * np],     plo[kb], vh);
                mma16816(oacc[2 * np + 1], plo[kb], vh + 2);
            }
        }
        __syncthreads();
    }

    // ---- normalize + store ----
    lsum0 += __shfl_xor_sync(0xffffffffu, lsum0, 1);
    lsum0 += __shfl_xor_sync(0xffffffffu, lsum0, 2);
    lsum1 += __shfl_xor_sync(0xffffffffu, lsum1, 1);
    lsum1 += __shfl_xor_sync(0xffffffffu, lsum1, 2);
    const float inv0 = 1.f / lsum0;
    const float inv1 = 1.f / lsum1;

    const int row0 = q0 + r0 + g;
    float* o0 = Og + ((size_t)b * SQ + row0) * (NH * HD) + (size_t)h * HD;
    float* o1 = o0 + 8 * (size_t)(NH * HD);
    #pragma unroll
    for (int nb = 0; nb < 16; nb++) {
        int col = nb * 8 + 2 * tg;
        *(float2*)(o0 + col) = make_float2(oacc[nb][0] * inv0, oacc[nb][1] * inv0);
        *(float2*)(o1 + col) = make_float2(oacc[nb][2] * inv1, oacc[nb][3] * inv1);
    }
}

extern "C" void kernel_launch(void* const* d_in, const int* in_sizes, int n_in,
                              void* d_out, int out_size)
{
    const float* Q = (const float*)d_in[0];
    const float* K = (const float*)d_in[1];
    const float* V = (const float*)d_in[2];
    float* O = (float*)d_out;

    prep_kv<<<KVELEMS / 4 / 256, 256>>>(K, V);

    cudaFuncSetAttribute(attn_hmma, cudaFuncAttributeMaxDynamicSharedMemorySize, SMEM_BYTES);
    dim3 grid(SQ / BM, NH, NBATCH);
    attn_hmma<<<grid, THREADS, SMEM_BYTES>>>(Q, O);
}